// round 7
// baseline (speedup 1.0000x reference)
#include <cuda_runtime.h>
#include <cuda_fp16.h>
#include <cstdint>
#include <math.h>
#include <mma.h>
using namespace nvcuda;

// ---------------- model constants ----------------
#define BATCH   512
#define S_LEN   215
#define DINP    36
#define DOB     4
#define DMODEL  144
#define DPE     16
#define DT      160
#define NHEAD   4
#define DH      40
#define NHID    128
#define FIN     860          // S_LEN * DOB
#define DFINAL  196          // DT + DINP
#define NROWS_GAT (BATCH*DINP)          // 18432
#define NROWS_TR  (S_LEN*BATCH)         // 110080

// ---------------- scratch (device globals; no allocation allowed) ----------------
__device__ float g_bufA[(size_t)BATCH*DINP*FIN];
__device__ float g_bufB[(size_t)BATCH*DINP*FIN];
__device__ float g_ps[NROWS_GAT];
__device__ float g_pd[NROWS_GAT];
__device__ float g_alpha1[(size_t)BATCH*DINP*DINP];
__device__ float g_alpha2[(size_t)BATCH*DINP*DINP];
__device__ float g_sq[BATCH];
__device__ float g_part[BATCH];
__device__ float g_x[(size_t)NROWS_TR*DT];
__device__ float g_qkv[(size_t)NROWS_TR*3*DT];
__device__ float g_att[(size_t)NROWS_TR*DT];
__device__ float g_tmp[(size_t)NROWS_TR*DT];
__device__ float g_ff[(size_t)NROWS_TR*NHID];
__device__ float g_feat[BATCH*DFINAL];
// fp16 GEMM operand mirrors (padded)
__device__ __half g_hA[(size_t)NROWS_TR*192];    // 21.1M halves (covers 18432*896 too)
__device__ __half g_hW[896*896];                 // transposed weights, Npad x Kp

// ---------------- utility ----------------
__global__ void zero_kernel(float* p, int n) {
    int i = blockIdx.x*blockDim.x + threadIdx.x;
    if (i < n) p[i] = 0.f;
}

__device__ __forceinline__ void cp16(uint32_t dst, const void* src) {
    asm volatile("cp.async.cg.shared.global [%0], [%1], 16;\n" :: "r"(dst), "l"(src));
}
__device__ __forceinline__ void cp_commit() {
    asm volatile("cp.async.commit_group;\n" ::: "memory");
}
__device__ __forceinline__ void cp_wait_all() {
    asm volatile("cp.async.wait_group 0;\n" ::: "memory");
}

// ---------------- operand conversion ----------------
// A: M x K fp32 -> M x Kp fp16 (zero pad)
__global__ void convA_kernel(const float* __restrict__ src, __half* __restrict__ dst,
                             int K, int Kp, size_t total)
{
    size_t i = (size_t)blockIdx.x*blockDim.x + threadIdx.x;
    if (i >= total) return;
    int c = (int)(i % Kp);
    size_t r = i / Kp;
    dst[i] = __float2half((c < K) ? src[r*K + c] : 0.f);
}
// B: K x N fp32 -> Npad x Kp fp16 transposed (zero pad)
__global__ void convBt_kernel(const float* __restrict__ B, __half* __restrict__ dst,
                              int K, int N, int Kp, int Npad)
{
    int i = blockIdx.x*blockDim.x + threadIdx.x;
    if (i >= Npad*Kp) return;
    int k = i % Kp, n = i / Kp;
    dst[i] = __float2half((k < K && n < N) ? B[(size_t)k*N + n] : 0.f);
}

// ---------------- FP16 tensor-core GEMM (cp.async double-buffered) ----------------
// C = act(Ah@Bh^T + bias + res). Ah: M x Kp fp16 (M%128==0, Kp%64==0),
// Bt: Npad x Kp fp16 (row n = column n of B). fp32 accumulate.
// Tile 128x128x64, 256 thr = 8 warps (2x4), warp tile 64x32 = 4x2 m16n16k16.
#define HKT 64
#define HLD 72     // smem ld (halves); 144B rows, bank-rotating
#define HSTG (128*HLD)
#define HSMEM (4*HSTG*2)   // 73728 B dynamic
#define WLD 20

__global__ void __launch_bounds__(256, 2)
hgemm16_kernel(const __half* __restrict__ Ah, const __half* __restrict__ Bt,
               float* __restrict__ C, int M, int N, int Kp,
               const float* __restrict__ bias,
               const float* __restrict__ res, int relu_flag)
{
    extern __shared__ __half hs[];
    __half* As0 = hs;
    __half* Bs0 = hs + HSTG;
    __half* As1 = hs + 2*HSTG;
    __half* Bs1 = hs + 3*HSTG;
    __shared__ float Wb[8][16*WLD];

    int tid = threadIdx.x;
    int warpId = tid >> 5, lane = tid & 31;
    int wr = warpId >> 2;     // 0..1
    int wc = warpId & 3;      // 0..3
    int row0 = blockIdx.y*128, col0 = blockIdx.x*128;

    wmma::fragment<wmma::accumulator,16,16,16,float> cf[4][2];
    #pragma unroll
    for (int i=0;i<4;i++)
      #pragma unroll
      for (int j=0;j<2;j++) wmma::fill_fragment(cf[i][j], 0.f);

    const int nIter = Kp / HKT;

    // stage loader: 128 rows x 64 halves each for A and B; 8 chunks/row
    auto load_stage = [&](__half* as, __half* bs, int k0) {
        #pragma unroll
        for (int c = 0; c < 4; c++) {
            int ci = tid + c*256;              // 0..1023
            int r = ci >> 3, c8 = (ci & 7)*8;
            cp16((uint32_t)__cvta_generic_to_shared(&as[r*HLD + c8]),
                 &Ah[(size_t)(row0 + r)*Kp + k0 + c8]);
        }
        #pragma unroll
        for (int c = 0; c < 4; c++) {
            int ci = tid + c*256;
            int r = ci >> 3, c8 = (ci & 7)*8;
            cp16((uint32_t)__cvta_generic_to_shared(&bs[r*HLD + c8]),
                 &Bt[(size_t)(col0 + r)*Kp + k0 + c8]);
        }
        cp_commit();
    };

    load_stage(As0, Bs0, 0);

    for (int it = 0; it < nIter; it++) {
        cp_wait_all();
        __syncthreads();
        __half* as = (it & 1) ? As1 : As0;
        __half* bs = (it & 1) ? Bs1 : Bs0;
        if (it + 1 < nIter)
            load_stage((it & 1) ? As0 : As1, (it & 1) ? Bs0 : Bs1, (it+1)*HKT);

        #pragma unroll
        for (int ks = 0; ks < HKT; ks += 16) {
            wmma::fragment<wmma::matrix_a,16,16,16,__half,wmma::row_major> af[4];
            wmma::fragment<wmma::matrix_b,16,16,16,__half,wmma::col_major> bf[2];
            #pragma unroll
            for (int fr=0; fr<4; fr++)
                wmma::load_matrix_sync(af[fr], &as[(wr*64 + fr*16)*HLD + ks], HLD);
            #pragma unroll
            for (int fc=0; fc<2; fc++)
                wmma::load_matrix_sync(bf[fc], &bs[(wc*32 + fc*16)*HLD + ks], HLD);
            #pragma unroll
            for (int fr=0; fr<4; fr++)
              #pragma unroll
              for (int fc=0; fc<2; fc++)
                wmma::mma_sync(cf[fr][fc], af[fr], bf[fc], cf[fr][fc]);
        }
        __syncthreads();
    }

    // ---- epilogue: per-warp staging, fused bias/res/relu ----
    float* wbuf = Wb[warpId];
    #pragma unroll
    for (int fr=0; fr<4; fr++) {
        #pragma unroll
        for (int fc=0; fc<2; fc++) {
            wmma::store_matrix_sync(wbuf, cf[fr][fc], WLD, wmma::mem_row_major);
            __syncwarp();
            int rb = row0 + wr*64 + fr*16;
            int cb = col0 + wc*32 + fc*16;
            #pragma unroll
            for (int i = lane; i < 256; i += 32) {
                int r = i >> 4, c = i & 15;
                int gc = cb + c;
                if (gc < N) {
                    float v = wbuf[r*WLD + c];
                    if (bias) v += bias[gc];
                    size_t off = (size_t)(rb + r)*N + gc;
                    if (res)  v += res[off];
                    if (relu_flag) v = fmaxf(v, 0.f);
                    C[off] = v;
                }
            }
            __syncwarp();
        }
    }
}

// ---------------- GAT ----------------
__global__ void build_x_kernel(const float* __restrict__ src, const float* __restrict__ R_u)
{
    size_t n = (size_t)blockIdx.x*blockDim.x + threadIdx.x;
    const size_t total = (size_t)BATCH*DINP*FIN;
    if (n >= total) return;
    int c = (int)(n % FIN);
    int i = (int)((n / FIN) % DINP);
    int b = (int)(n / ((size_t)FIN*DINP));
    int s = c >> 2, o = c & 3;
    float v = src[((size_t)s*BATCH + b)*(2*DINP) + i];
    g_bufA[n] = fmaxf(v * R_u[i*4+o], 0.f);
}

__global__ void psd_kernel(const float* __restrict__ XP,
                           const float* __restrict__ a_s, const float* __restrict__ a_d)
{
    int row = blockIdx.x;
    const float* x = XP + (size_t)row*FIN;
    int t = threadIdx.x;
    float s1=0.f, s2=0.f;
    for (int c=t; c<FIN; c+=256) { float v=x[c]; s1 += v*a_s[c]; s2 += v*a_d[c]; }
    __shared__ float r1[256], r2[256];
    r1[t]=s1; r2[t]=s2; __syncthreads();
    for (int o=128;o>0;o>>=1){ if(t<o){r1[t]+=r1[t+o]; r2[t]+=r2[t+o];} __syncthreads(); }
    if (t==0){ g_ps[row]=r1[0]; g_pd[row]=r2[0]; }
}

__global__ void alpha_kernel(const float* __restrict__ edge, float* __restrict__ alpha)
{
    int b = blockIdx.x;
    int i = threadIdx.x;
    if (i >= DINP) return;
    const float* psb = g_ps + b*DINP;
    float pdi = g_pd[b*DINP+i];
    float e[DINP];
    float m = -1e30f;
    #pragma unroll
    for (int j=0;j<DINP;j++){
        float v = pdi + psb[j];
        v = (v > 0.f) ? v : 0.2f*v;
        e[j]=v; m = fmaxf(m,v);
    }
    float l=0.f;
    #pragma unroll
    for (int j=0;j<DINP;j++){ float w=expf(e[j]-m); e[j]=w; l+=w; }
    float inv = 1.f/l;
    size_t base = ((size_t)b*DINP + i)*DINP;
    #pragma unroll
    for (int j=0;j<DINP;j++){
        float a = e[j]*inv;
        if (edge) a *= edge[base+j];
        alpha[base+j] = a;
    }
}

__global__ void gat_agg_kernel(const float* __restrict__ alpha, const float* __restrict__ XP,
                               float* __restrict__ H)
{
    int b = blockIdx.x;
    __shared__ float al[DINP*DINP];
    for (int i=threadIdx.x;i<DINP*DINP;i+=blockDim.x) al[i]=alpha[(size_t)b*DINP*DINP+i];
    __syncthreads();
    const float* xp = XP + (size_t)b*DINP*FIN;
    float* hb = H + (size_t)b*DINP*FIN;
    for (int idx=threadIdx.x; idx<DINP*FIN; idx+=blockDim.x){
        int i = idx/FIN, c = idx%FIN;
        float s=0.f;
        #pragma unroll 6
        for (int j=0;j<DINP;j++) s += al[i*DINP+j]*xp[(size_t)j*FIN+c];
        hb[idx]=s;
    }
}

__global__ void sq_kernel(const float* __restrict__ A)
{
    int b = blockIdx.x; int t = threadIdx.x;
    float s=0.f;
    for (int i=t;i<DINP*DINP;i+=256){ float v=A[(size_t)b*DINP*DINP+i]; s+=v*v; }
    __shared__ float r[256];
    r[t]=s; __syncthreads();
    for (int o=128;o>0;o>>=1){ if(t<o) r[t]+=r[t+o]; __syncthreads(); }
    if (t==0) g_sq[b]=r[0];
}

__global__ void dist_kernel(const float* __restrict__ A)
{
    int i = blockIdx.x; int t = threadIdx.x;
    __shared__ float Ai[DINP*DINP];
    for (int c=t;c<DINP*DINP;c+=256) Ai[c]=A[(size_t)i*DINP*DINP+c];
    __syncthreads();
    float local=0.f;
    for (int j=t;j<BATCH;j+=256){
        const float* Aj = A + (size_t)j*DINP*DINP;
        float dot=0.f;
        for (int c=0;c<DINP*DINP;c++) dot += Ai[c]*Aj[c];
        float d2 = g_sq[i]+g_sq[j]-2.f*dot;
        d2 = fmaxf(d2, 0.f);
        local += sqrtf(d2 + 1e-12f);
    }
    __shared__ float r[256];
    r[t]=local; __syncthreads();
    for (int o=128;o>0;o>>=1){ if(t<o) r[t]+=r[t+o]; __syncthreads(); }
    if (t==0) g_part[i]=r[0];
}

__global__ void fin_dist_kernel(float* __restrict__ out, int out_size)
{
    if (threadIdx.x==0){
        float s=0.f;
        for (int i=0;i<BATCH;i++) s += g_part[i];
        if (out_size > BATCH*2) out[BATCH*2] = s / ((float)BATCH*(float)BATCH);
    }
}

// ---------------- transformer input ----------------
__global__ void build_out_kernel(const float* __restrict__ times)
{
    size_t n = (size_t)blockIdx.x*blockDim.x + threadIdx.x;
    const size_t total = (size_t)NROWS_TR*DT;
    if (n >= total) return;
    int d = (int)(n % DT);
    int b = (int)((n / DT) % BATCH);
    int s = (int)(n / ((size_t)DT*BATCH));
    float v;
    if (d < DMODEL) {
        v = g_bufA[((size_t)b*DINP + (d>>2))*FIN + s*4 + (d&3)];
    } else {
        int k = d - DMODEL;
        float tv = times[(size_t)s*BATCH + b];
        int kk = (k < 8) ? k : k-8;
        float ts = powf(215.0f, (float)kk/7.0f) * 100.0f;
        float sc = tv / ts;
        v = (k < 8) ? sinf(sc) : cosf(sc);
    }
    g_x[n] = v;
}

// ---------------- attention (single pass; scores bounded, exp safe) ----------------
#define ATTN_SMEM (2*S_LEN*DH*4)   // 68800 B
__global__ void attn_kernel(const float* __restrict__ qkv, const int* __restrict__ lengths,
                            float* __restrict__ out)
{
    extern __shared__ float smA[];
    float* Ks = smA;
    float* Vs = smA + S_LEN*DH;
    int b = blockIdx.x, h = blockIdx.y;
    int len = lengths[b];
    for (int i = threadIdx.x; i < S_LEN*DH; i += blockDim.x) {
        int t = i / DH, d = i % DH;
        size_t base = ((size_t)t*BATCH + b)*(3*DT) + h*DH + d;
        Ks[i] = qkv[base + DT];
        Vs[i] = qkv[base + 2*DT];
    }
    __syncthreads();
    int s = threadIdx.x;
    if (s >= S_LEN) return;
    float q[DH];
    {
        size_t qb = ((size_t)s*BATCH + b)*(3*DT) + h*DH;
        #pragma unroll
        for (int d=0; d<DH; d++) q[d] = qkv[qb + d];
    }
    const float scale = rsqrtf((float)DH);
    float l = 0.f;
    float acc[DH];
    #pragma unroll
    for (int d=0; d<DH; d++) acc[d]=0.f;
    for (int t=0; t<len; t++) {
        float sc = 0.f;
        #pragma unroll
        for (int d=0; d<DH; d++) sc += q[d]*Ks[t*DH+d];
        float w = expf(sc*scale);        // softmax shift-invariant; |sc*scale| << 88
        l += w;
        #pragma unroll
        for (int d=0; d<DH; d++) acc[d] += w*Vs[t*DH+d];
    }
    float inv = 1.f/l;
    size_t ob = ((size_t)s*BATCH + b)*DT + h*DH;
    #pragma unroll
    for (int d=0; d<DH; d++) out[ob + d] = acc[d]*inv;
}

// ---------------- layernorm ----------------
__global__ void ln_kernel(const float* __restrict__ x, float* __restrict__ y,
                          const float* __restrict__ g, const float* __restrict__ bta)
{
    int row = blockIdx.x;
    const float* xr = x + (size_t)row*DT;
    int t = threadIdx.x;
    float v = xr[t];
    __shared__ float s1[DT], s2[DT];
    s1[t]=v; s2[t]=v*v; __syncthreads();
    if (t < 32) {
        float a=0.f, q=0.f;
        for (int i=t;i<DT;i+=32){ a+=s1[i]; q+=s2[i]; }
        for (int o=16;o>0;o>>=1){ a+=__shfl_down_sync(0xffffffff,a,o); q+=__shfl_down_sync(0xffffffff,q,o); }
        if (t==0){ s1[0]=a; s2[0]=q; }
    }
    __syncthreads();
    float mean = s1[0]/(float)DT;
    float var  = s2[0]/(float)DT - mean*mean;
    y[(size_t)row*DT + t] = (v-mean)*rsqrtf(var+1e-5f)*g[t] + bta[t];
}

// ---------------- pooled features + static embedding ----------------
__global__ void agg_emb_kernel(const int* __restrict__ lengths,
                               const float* __restrict__ statics,
                               const float* __restrict__ emb_w, const float* __restrict__ emb_b)
{
    int b = blockIdx.x; int d = threadIdx.x;
    int len = lengths[b];
    if (d < DT) {
        float s = 0.f;
        for (int t=0;t<len;t++) s += g_x[((size_t)t*BATCH + b)*DT + d];
        g_feat[b*DFINAL+d] = s / ((float)len + 1.0f);
    } else if (d < DFINAL) {
        int j = d - DT;
        float s = emb_b[j];
        #pragma unroll
        for (int r=0;r<9;r++) s += statics[b*9+r]*emb_w[r*DINP+j];
        g_feat[b*DFINAL+d] = s;
    }
}

// ---------------- final MLP ----------------
__global__ void mlp_kernel(const float* __restrict__ w1, const float* __restrict__ b1,
                           const float* __restrict__ w2, const float* __restrict__ b2,
                           float* __restrict__ out)
{
    int b = blockIdx.x; int t = threadIdx.x;
    __shared__ float f[DFINAL], hd[DFINAL];
    f[t] = g_feat[b*DFINAL+t];
    __syncthreads();
    float s = b1[t];
    for (int r=0;r<DFINAL;r++) s += f[r]*w1[r*DFINAL+t];
    hd[t] = fmaxf(s, 0.f);
    __syncthreads();
    if (t < 2) {
        float s2 = b2[t];
        for (int r=0;r<DFINAL;r++) s2 += hd[r]*w2[r*2+t];
        out[b*2+t] = s2;
    }
}

// ---------------- launch ----------------
extern "C" void kernel_launch(void* const* d_in, const int* in_sizes, int n_in,
                              void* d_out, int out_size)
{
    const float* src    = (const float*)d_in[0];
    const float* statics= (const float*)d_in[1];
    const float* times  = (const float*)d_in[2];
    const int*   lengths= (const int*)d_in[3];
    const float* R_u    = (const float*)d_in[4];
    const float* emb_w  = (const float*)d_in[5];
    const float* emb_b  = (const float*)d_in[6];
    const float* W1     = (const float*)d_in[7];
    const float* a1_s   = (const float*)d_in[8];
    const float* a1_d   = (const float*)d_in[9];
    const float* W2     = (const float*)d_in[10];
    const float* a2_s   = (const float*)d_in[11];
    const float* a2_d   = (const float*)d_in[12];
    const float* attn_in_w  = (const float*)d_in[13];
    const float* attn_in_b  = (const float*)d_in[14];
    const float* attn_out_w = (const float*)d_in[15];
    const float* attn_out_b = (const float*)d_in[16];
    const float* ff1_w  = (const float*)d_in[17];
    const float* ff1_b  = (const float*)d_in[18];
    const float* ff2_w  = (const float*)d_in[19];
    const float* ff2_b  = (const float*)d_in[20];
    const float* ln1_g  = (const float*)d_in[21];
    const float* ln1_b  = (const float*)d_in[22];
    const float* ln2_g  = (const float*)d_in[23];
    const float* ln2_b  = (const float*)d_in[24];
    const float* mlp1_w = (const float*)d_in[25];
    const float* mlp1_b = (const float*)d_in[26];
    const float* mlp2_w = (const float*)d_in[27];
    const float* mlp2_b = (const float*)d_in[28];
    float* out = (float*)d_out;

    float *bufA, *bufB, *al1, *al2, *x, *qkv, *att, *tmp, *ff;
    __half *hA, *hW;
    cudaGetSymbolAddress((void**)&bufA, g_bufA);
    cudaGetSymbolAddress((void**)&bufB, g_bufB);
    cudaGetSymbolAddress((void**)&al1,  g_alpha1);
    cudaGetSymbolAddress((void**)&al2,  g_alpha2);
    cudaGetSymbolAddress((void**)&x,    g_x);
    cudaGetSymbolAddress((void**)&qkv,  g_qkv);
    cudaGetSymbolAddress((void**)&att,  g_att);
    cudaGetSymbolAddress((void**)&tmp,  g_tmp);
    cudaGetSymbolAddress((void**)&ff,   g_ff);
    cudaGetSymbolAddress((void**)&hA,   g_hA);
    cudaGetSymbolAddress((void**)&hW,   g_hW);

    static bool attr_done = false;
    if (!attr_done) {
        cudaFuncSetAttribute(attn_kernel,
                             cudaFuncAttributeMaxDynamicSharedMemorySize, ATTN_SMEM);
        cudaFuncSetAttribute(hgemm16_kernel,
                             cudaFuncAttributeMaxDynamicSharedMemorySize, HSMEM);
        attr_done = true;
    }

    // fused convert+GEMM launcher: C = act(A(MxK) @ B(KxN) + bias + res)
    auto gemm = [&](const float* A, const float* B, float* C,
                    int M, int K, int N,
                    const float* bias, const float* res, int relu) {
        int Kp = ((K + HKT - 1)/HKT)*HKT;
        int Npad = ((N + 127)/128)*128;
        size_t ta = (size_t)M*Kp;
        convA_kernel<<<(unsigned)((ta+255)/256),256>>>(A, hA, K, Kp, ta);
        convBt_kernel<<<(Npad*Kp+255)/256,256>>>(B, hW, K, N, Kp, Npad);
        dim3 g(Npad/128, M/128);
        hgemm16_kernel<<<g,256,HSMEM>>>(hA, hW, C, M, N, Kp, bias, res, relu);
    };

    zero_kernel<<<(out_size+255)/256, 256>>>(out, out_size);

    // ----- GAT -----
    {
        size_t nx = (size_t)BATCH*DINP*FIN;
        build_x_kernel<<<(unsigned)((nx+255)/256), 256>>>(src, R_u);
        gemm(bufA, W1, bufB, NROWS_GAT, FIN, FIN, nullptr, nullptr, 0);
        psd_kernel<<<NROWS_GAT,256>>>(bufB, a1_s, a1_d);
        alpha_kernel<<<BATCH,64>>>(nullptr, al1);
        gat_agg_kernel<<<BATCH,256>>>(al1, bufB, bufA);
        gemm(bufA, W2, bufB, NROWS_GAT, FIN, FIN, nullptr, nullptr, 0);
        psd_kernel<<<NROWS_GAT,256>>>(bufB, a2_s, a2_d);
        alpha_kernel<<<BATCH,64>>>(al1, al2);
        gat_agg_kernel<<<BATCH,256>>>(al2, bufB, bufA);
        sq_kernel<<<BATCH,256>>>(al2);
        dist_kernel<<<BATCH,256>>>(al2);
        fin_dist_kernel<<<1,32>>>(out, out_size);
    }

    // ----- transformer -----
    {
        size_t no = (size_t)NROWS_TR*DT;
        build_out_kernel<<<(unsigned)((no+255)/256), 256>>>(times);
        for (int l=0; l<2; l++) {
            gemm(x, attn_in_w + (size_t)l*DT*3*DT, qkv,
                 NROWS_TR, DT, 3*DT, attn_in_b + l*3*DT, nullptr, 0);
            attn_kernel<<<dim3(BATCH,NHEAD),256,ATTN_SMEM>>>(qkv, lengths, att);
            gemm(att, attn_out_w + (size_t)l*DT*DT, tmp,
                 NROWS_TR, DT, DT, attn_out_b + l*DT, x, 0);
            ln_kernel<<<NROWS_TR,DT>>>(tmp, x, ln1_g + l*DT, ln1_b + l*DT);
            gemm(x, ff1_w + (size_t)l*DT*NHID, ff,
                 NROWS_TR, DT, NHID, ff1_b + l*NHID, nullptr, 1);
            gemm(ff, ff2_w + (size_t)l*NHID*DT, tmp,
                 NROWS_TR, NHID, DT, ff2_b + l*DT, x, 0);
            ln_kernel<<<NROWS_TR,DT>>>(tmp, x, ln2_g + l*DT, ln2_b + l*DT);
        }
    }

    // ----- head -----
    agg_emb_kernel<<<BATCH,DFINAL>>>(lengths, statics, emb_w, emb_b);
    mlp_kernel<<<BATCH,DFINAL>>>(mlp1_w, mlp1_b, mlp2_w, mlp2_b, out);
}

// round 8
// speedup vs baseline: 1.0262x; 1.0262x over previous
#include <cuda_runtime.h>
#include <cuda_fp16.h>
#include <cstdint>
#include <math.h>
#include <mma.h>
using namespace nvcuda;

// ---------------- model constants ----------------
#define BATCH   512
#define S_LEN   215
#define DINP    36
#define DOB     4
#define DMODEL  144
#define DPE     16
#define DT      160
#define NHEAD   4
#define DH      40
#define NHID    128
#define FIN     860          // S_LEN * DOB
#define DFINAL  196          // DT + DINP
#define NROWS_GAT (BATCH*DINP)          // 18432
#define NROWS_TR  (S_LEN*BATCH)         // 110080

// ---------------- scratch (device globals; no allocation allowed) ----------------
__device__ float g_bufA[(size_t)BATCH*DINP*FIN];
__device__ float g_bufB[(size_t)BATCH*DINP*FIN];
__device__ float g_ps[NROWS_GAT];
__device__ float g_pd[NROWS_GAT];
__device__ float g_alpha1[(size_t)BATCH*DINP*DINP];
__device__ float g_alpha2[(size_t)BATCH*DINP*DINP];
__device__ float g_sq[BATCH];
__device__ float g_part[BATCH];
__device__ float g_x[(size_t)NROWS_TR*DT];
__device__ float g_qkv[(size_t)NROWS_TR*3*DT];
__device__ float g_att[(size_t)NROWS_TR*DT];
__device__ float g_tmp[(size_t)NROWS_TR*DT];
__device__ float g_ff[(size_t)NROWS_TR*NHID];
__device__ float g_feat[BATCH*DFINAL];
// fp16 GEMM operand mirrors (padded)
__device__ __half g_hA[(size_t)NROWS_TR*192];    // covers 18432*896 too
__device__ __half g_hW[896*896];                 // transposed weights, Npad x Kp

// ---------------- utility ----------------
__global__ void zero_kernel(float* p, int n) {
    int i = blockIdx.x*blockDim.x + threadIdx.x;
    if (i < n) p[i] = 0.f;
}

__device__ __forceinline__ void cp16(uint32_t dst, const void* src) {
    asm volatile("cp.async.cg.shared.global [%0], [%1], 16;\n" :: "r"(dst), "l"(src));
}
__device__ __forceinline__ void cp_commit() {
    asm volatile("cp.async.commit_group;\n" ::: "memory");
}
__device__ __forceinline__ void cp_wait_all() {
    asm volatile("cp.async.wait_group 0;\n" ::: "memory");
}

// ---------------- operand conversion ----------------
__global__ void convA_kernel(const float* __restrict__ src, __half* __restrict__ dst,
                             int K, int Kp, size_t total)
{
    size_t i = (size_t)blockIdx.x*blockDim.x + threadIdx.x;
    if (i >= total) return;
    int c = (int)(i % Kp);
    size_t r = i / Kp;
    dst[i] = __float2half((c < K) ? src[r*K + c] : 0.f);
}
__global__ void convBt_kernel(const float* __restrict__ B, __half* __restrict__ dst,
                              int K, int N, int Kp, int Npad)
{
    int i = blockIdx.x*blockDim.x + threadIdx.x;
    if (i >= Npad*Kp) return;
    int k = i % Kp, n = i / Kp;
    dst[i] = __float2half((k < K && n < N) ? B[(size_t)k*N + n] : 0.f);
}

// ---------------- FP16 tensor-core GEMM ----------------
// C = act(Ah@Bt^T + bias + res). Ah: M x Kp fp16 (M%128==0, Kp%64==0),
// Bt: Npad x Kp fp16. fp32 accumulate.
// CTA tile 128x128x64 double-buffered; 128 thr = 4 warps (2x2), warp tile 64x64.
#define HKT 64
#define HLD 72     // smem ld (halves); 144B rows, bank-rotating
#define HSTG (128*HLD)
#define HSMEM (4*HSTG*2)   // 73728 B dynamic
#define WLD 20

__global__ void __launch_bounds__(128)
hgemm16_kernel(const __half* __restrict__ Ah, const __half* __restrict__ Bt,
               float* __restrict__ C, int M, int N, int Kp,
               const float* __restrict__ bias,
               const float* __restrict__ res, int relu_flag)
{
    extern __shared__ __half hs[];
    __half* As0 = hs;
    __half* Bs0 = hs + HSTG;
    __half* As1 = hs + 2*HSTG;
    __half* Bs1 = hs + 3*HSTG;
    __shared__ float Wb[4][16*WLD];

    int tid = threadIdx.x;
    int warpId = tid >> 5, lane = tid & 31;
    int wr = warpId >> 1;     // 0..1 -> row offset wr*64
    int wc = warpId & 1;      // 0..1 -> col offset wc*64
    int row0 = blockIdx.y*128, col0 = blockIdx.x*128;

    wmma::fragment<wmma::accumulator,16,16,16,float> cf[4][4];
    #pragma unroll
    for (int i=0;i<4;i++)
      #pragma unroll
      for (int j=0;j<4;j++) wmma::fill_fragment(cf[i][j], 0.f);

    const int nIter = Kp / HKT;

    // stage loader: 128 rows x 64 halves each for A and B; 8 chunks per thread each
    auto load_stage = [&](__half* as, __half* bs, int k0) {
        #pragma unroll
        for (int c = 0; c < 8; c++) {
            int ci = tid + c*128;              // 0..1023
            int r = ci >> 3, c8 = (ci & 7)*8;
            cp16((uint32_t)__cvta_generic_to_shared(&as[r*HLD + c8]),
                 &Ah[(size_t)(row0 + r)*Kp + k0 + c8]);
        }
        #pragma unroll
        for (int c = 0; c < 8; c++) {
            int ci = tid + c*128;
            int r = ci >> 3, c8 = (ci & 7)*8;
            cp16((uint32_t)__cvta_generic_to_shared(&bs[r*HLD + c8]),
                 &Bt[(size_t)(col0 + r)*Kp + k0 + c8]);
        }
        cp_commit();
    };

    load_stage(As0, Bs0, 0);

    for (int it = 0; it < nIter; it++) {
        cp_wait_all();
        __syncthreads();
        __half* as = (it & 1) ? As1 : As0;
        __half* bs = (it & 1) ? Bs1 : Bs0;
        if (it + 1 < nIter)
            load_stage((it & 1) ? As0 : As1, (it & 1) ? Bs0 : Bs1, (it+1)*HKT);

        #pragma unroll
        for (int ks = 0; ks < HKT; ks += 16) {
            wmma::fragment<wmma::matrix_a,16,16,16,__half,wmma::row_major> af[4];
            wmma::fragment<wmma::matrix_b,16,16,16,__half,wmma::col_major> bf[4];
            #pragma unroll
            for (int fr=0; fr<4; fr++)
                wmma::load_matrix_sync(af[fr], &as[(wr*64 + fr*16)*HLD + ks], HLD);
            #pragma unroll
            for (int fc=0; fc<4; fc++)
                wmma::load_matrix_sync(bf[fc], &bs[(wc*64 + fc*16)*HLD + ks], HLD);
            #pragma unroll
            for (int fr=0; fr<4; fr++)
              #pragma unroll
              for (int fc=0; fc<4; fc++)
                wmma::mma_sync(cf[fr][fc], af[fr], bf[fc], cf[fr][fc]);
        }
        __syncthreads();
    }

    // ---- epilogue: per-warp staging, fused bias/res/relu ----
    float* wbuf = Wb[warpId];
    #pragma unroll
    for (int fr=0; fr<4; fr++) {
        #pragma unroll
        for (int fc=0; fc<4; fc++) {
            wmma::store_matrix_sync(wbuf, cf[fr][fc], WLD, wmma::mem_row_major);
            __syncwarp();
            int rb = row0 + wr*64 + fr*16;
            int cb = col0 + wc*64 + fc*16;
            #pragma unroll
            for (int i = lane; i < 256; i += 32) {
                int r = i >> 4, c = i & 15;
                int gc = cb + c;
                if (gc < N) {
                    float v = wbuf[r*WLD + c];
                    if (bias) v += bias[gc];
                    size_t off = (size_t)(rb + r)*N + gc;
                    if (res)  v += res[off];
                    if (relu_flag) v = fmaxf(v, 0.f);
                    C[off] = v;
                }
            }
            __syncwarp();
        }
    }
}

// ---------------- GAT ----------------
__global__ void build_x_kernel(const float* __restrict__ src, const float* __restrict__ R_u)
{
    size_t n = (size_t)blockIdx.x*blockDim.x + threadIdx.x;
    const size_t total = (size_t)BATCH*DINP*FIN;
    if (n >= total) return;
    int c = (int)(n % FIN);
    int i = (int)((n / FIN) % DINP);
    int b = (int)(n / ((size_t)FIN*DINP));
    int s = c >> 2, o = c & 3;
    float v = src[((size_t)s*BATCH + b)*(2*DINP) + i];
    g_bufA[n] = fmaxf(v * R_u[i*4+o], 0.f);
}

__global__ void psd_kernel(const float* __restrict__ XP,
                           const float* __restrict__ a_s, const float* __restrict__ a_d)
{
    int row = blockIdx.x;
    const float* x = XP + (size_t)row*FIN;
    int t = threadIdx.x;
    float s1=0.f, s2=0.f;
    for (int c=t; c<FIN; c+=256) { float v=x[c]; s1 += v*a_s[c]; s2 += v*a_d[c]; }
    __shared__ float r1[256], r2[256];
    r1[t]=s1; r2[t]=s2; __syncthreads();
    for (int o=128;o>0;o>>=1){ if(t<o){r1[t]+=r1[t+o]; r2[t]+=r2[t+o];} __syncthreads(); }
    if (t==0){ g_ps[row]=r1[0]; g_pd[row]=r2[0]; }
}

__global__ void alpha_kernel(const float* __restrict__ edge, float* __restrict__ alpha)
{
    int b = blockIdx.x;
    int i = threadIdx.x;
    if (i >= DINP) return;
    const float* psb = g_ps + b*DINP;
    float pdi = g_pd[b*DINP+i];
    float e[DINP];
    float m = -1e30f;
    #pragma unroll
    for (int j=0;j<DINP;j++){
        float v = pdi + psb[j];
        v = (v > 0.f) ? v : 0.2f*v;
        e[j]=v; m = fmaxf(m,v);
    }
    float l=0.f;
    #pragma unroll
    for (int j=0;j<DINP;j++){ float w=expf(e[j]-m); e[j]=w; l+=w; }
    float inv = 1.f/l;
    size_t base = ((size_t)b*DINP + i)*DINP;
    #pragma unroll
    for (int j=0;j<DINP;j++){
        float a = e[j]*inv;
        if (edge) a *= edge[base+j];
        alpha[base+j] = a;
    }
}

__global__ void gat_agg_kernel(const float* __restrict__ alpha, const float* __restrict__ XP,
                               float* __restrict__ H)
{
    int b = blockIdx.x;
    __shared__ float al[DINP*DINP];
    for (int i=threadIdx.x;i<DINP*DINP;i+=blockDim.x) al[i]=alpha[(size_t)b*DINP*DINP+i];
    __syncthreads();
    const float* xp = XP + (size_t)b*DINP*FIN;
    float* hb = H + (size_t)b*DINP*FIN;
    for (int idx=threadIdx.x; idx<DINP*FIN; idx+=blockDim.x){
        int i = idx/FIN, c = idx%FIN;
        float s=0.f;
        #pragma unroll 6
        for (int j=0;j<DINP;j++) s += al[i*DINP+j]*xp[(size_t)j*FIN+c];
        hb[idx]=s;
    }
}

__global__ void sq_kernel(const float* __restrict__ A)
{
    int b = blockIdx.x; int t = threadIdx.x;
    float s=0.f;
    for (int i=t;i<DINP*DINP;i+=256){ float v=A[(size_t)b*DINP*DINP+i]; s+=v*v; }
    __shared__ float r[256];
    r[t]=s; __syncthreads();
    for (int o=128;o>0;o>>=1){ if(t<o) r[t]+=r[t+o]; __syncthreads(); }
    if (t==0) g_sq[b]=r[0];
}

__global__ void dist_kernel(const float* __restrict__ A)
{
    int i = blockIdx.x; int t = threadIdx.x;
    __shared__ float Ai[DINP*DINP];
    for (int c=t;c<DINP*DINP;c+=256) Ai[c]=A[(size_t)i*DINP*DINP+c];
    __syncthreads();
    float local=0.f;
    for (int j=t;j<BATCH;j+=256){
        const float* Aj = A + (size_t)j*DINP*DINP;
        float dot=0.f;
        for (int c=0;c<DINP*DINP;c++) dot += Ai[c]*Aj[c];
        float d2 = g_sq[i]+g_sq[j]-2.f*dot;
        d2 = fmaxf(d2, 0.f);
        local += sqrtf(d2 + 1e-12f);
    }
    __shared__ float r[256];
    r[t]=local; __syncthreads();
    for (int o=128;o>0;o>>=1){ if(t<o) r[t]+=r[t+o]; __syncthreads(); }
    if (t==0) g_part[i]=r[0];
}

__global__ void fin_dist_kernel(float* __restrict__ out, int out_size)
{
    if (threadIdx.x==0){
        float s=0.f;
        for (int i=0;i<BATCH;i++) s += g_part[i];
        if (out_size > BATCH*2) out[BATCH*2] = s / ((float)BATCH*(float)BATCH);
    }
}

// ---------------- transformer input ----------------
__global__ void build_out_kernel(const float* __restrict__ times)
{
    size_t n = (size_t)blockIdx.x*blockDim.x + threadIdx.x;
    const size_t total = (size_t)NROWS_TR*DT;
    if (n >= total) return;
    int d = (int)(n % DT);
    int b = (int)((n / DT) % BATCH);
    int s = (int)(n / ((size_t)DT*BATCH));
    float v;
    if (d < DMODEL) {
        v = g_bufA[((size_t)b*DINP + (d>>2))*FIN + s*4 + (d&3)];
    } else {
        int k = d - DMODEL;
        float tv = times[(size_t)s*BATCH + b];
        int kk = (k < 8) ? k : k-8;
        float ts = powf(215.0f, (float)kk/7.0f) * 100.0f;
        float sc = tv / ts;
        v = (k < 8) ? sinf(sc) : cosf(sc);
    }
    g_x[n] = v;
}

// ---------------- attention (single pass; scores bounded, exp safe) ----------------
#define ATTN_SMEM (2*S_LEN*DH*4)   // 68800 B
__global__ void attn_kernel(const float* __restrict__ qkv, const int* __restrict__ lengths,
                            float* __restrict__ out)
{
    extern __shared__ float smA[];
    float* Ks = smA;
    float* Vs = smA + S_LEN*DH;
    int b = blockIdx.x, h = blockIdx.y;
    int len = lengths[b];
    for (int i = threadIdx.x; i < S_LEN*DH; i += blockDim.x) {
        int t = i / DH, d = i % DH;
        size_t base = ((size_t)t*BATCH + b)*(3*DT) + h*DH + d;
        Ks[i] = qkv[base + DT];
        Vs[i] = qkv[base + 2*DT];
    }
    __syncthreads();
    int s = threadIdx.x;
    if (s >= S_LEN) return;
    float q[DH];
    {
        size_t qb = ((size_t)s*BATCH + b)*(3*DT) + h*DH;
        #pragma unroll
        for (int d=0; d<DH; d++) q[d] = qkv[qb + d];
    }
    const float scale = rsqrtf((float)DH);
    float l = 0.f;
    float acc[DH];
    #pragma unroll
    for (int d=0; d<DH; d++) acc[d]=0.f;
    for (int t=0; t<len; t++) {
        float sc = 0.f;
        #pragma unroll
        for (int d=0; d<DH; d++) sc += q[d]*Ks[t*DH+d];
        float w = expf(sc*scale);
        l += w;
        #pragma unroll
        for (int d=0; d<DH; d++) acc[d] += w*Vs[t*DH+d];
    }
    float inv = 1.f/l;
    size_t ob = ((size_t)s*BATCH + b)*DT + h*DH;
    #pragma unroll
    for (int d=0; d<DH; d++) out[ob + d] = acc[d]*inv;
}

// ---------------- layernorm ----------------
__global__ void ln_kernel(const float* __restrict__ x, float* __restrict__ y,
                          const float* __restrict__ g, const float* __restrict__ bta)
{
    int row = blockIdx.x;
    const float* xr = x + (size_t)row*DT;
    int t = threadIdx.x;
    float v = xr[t];
    __shared__ float s1[DT], s2[DT];
    s1[t]=v; s2[t]=v*v; __syncthreads();
    if (t < 32) {
        float a=0.f, q=0.f;
        for (int i=t;i<DT;i+=32){ a+=s1[i]; q+=s2[i]; }
        for (int o=16;o>0;o>>=1){ a+=__shfl_down_sync(0xffffffff,a,o); q+=__shfl_down_sync(0xffffffff,q,o); }
        if (t==0){ s1[0]=a; s2[0]=q; }
    }
    __syncthreads();
    float mean = s1[0]/(float)DT;
    float var  = s2[0]/(float)DT - mean*mean;
    y[(size_t)row*DT + t] = (v-mean)*rsqrtf(var+1e-5f)*g[t] + bta[t];
}

// ---------------- pooled features + static embedding ----------------
__global__ void agg_emb_kernel(const int* __restrict__ lengths,
                               const float* __restrict__ statics,
                               const float* __restrict__ emb_w, const float* __restrict__ emb_b)
{
    int b = blockIdx.x; int d = threadIdx.x;
    int len = lengths[b];
    if (d < DT) {
        float s = 0.f;
        for (int t=0;t<len;t++) s += g_x[((size_t)t*BATCH + b)*DT + d];
        g_feat[b*DFINAL+d] = s / ((float)len + 1.0f);
    } else if (d < DFINAL) {
        int j = d - DT;
        float s = emb_b[j];
        #pragma unroll
        for (int r=0;r<9;r++) s += statics[b*9+r]*emb_w[r*DINP+j];
        g_feat[b*DFINAL+d] = s;
    }
}

// ---------------- final MLP ----------------
__global__ void mlp_kernel(const float* __restrict__ w1, const float* __restrict__ b1,
                           const float* __restrict__ w2, const float* __restrict__ b2,
                           float* __restrict__ out)
{
    int b = blockIdx.x; int t = threadIdx.x;
    __shared__ float f[DFINAL], hd[DFINAL];
    f[t] = g_feat[b*DFINAL+t];
    __syncthreads();
    float s = b1[t];
    for (int r=0;r<DFINAL;r++) s += f[r]*w1[r*DFINAL+t];
    hd[t] = fmaxf(s, 0.f);
    __syncthreads();
    if (t < 2) {
        float s2 = b2[t];
        for (int r=0;r<DFINAL;r++) s2 += hd[r]*w2[r*2+t];
        out[b*2+t] = s2;
    }
}

// ---------------- launch ----------------
extern "C" void kernel_launch(void* const* d_in, const int* in_sizes, int n_in,
                              void* d_out, int out_size)
{
    const float* src    = (const float*)d_in[0];
    const float* statics= (const float*)d_in[1];
    const float* times  = (const float*)d_in[2];
    const int*   lengths= (const int*)d_in[3];
    const float* R_u    = (const float*)d_in[4];
    const float* emb_w  = (const float*)d_in[5];
    const float* emb_b  = (const float*)d_in[6];
    const float* W1     = (const float*)d_in[7];
    const float* a1_s   = (const float*)d_in[8];
    const float* a1_d   = (const float*)d_in[9];
    const float* W2     = (const float*)d_in[10];
    const float* a2_s   = (const float*)d_in[11];
    const float* a2_d   = (const float*)d_in[12];
    const float* attn_in_w  = (const float*)d_in[13];
    const float* attn_in_b  = (const float*)d_in[14];
    const float* attn_out_w = (const float*)d_in[15];
    const float* attn_out_b = (const float*)d_in[16];
    const float* ff1_w  = (const float*)d_in[17];
    const float* ff1_b  = (const float*)d_in[18];
    const float* ff2_w  = (const float*)d_in[19];
    const float* ff2_b  = (const float*)d_in[20];
    const float* ln1_g  = (const float*)d_in[21];
    const float* ln1_b  = (const float*)d_in[22];
    const float* ln2_g  = (const float*)d_in[23];
    const float* ln2_b  = (const float*)d_in[24];
    const float* mlp1_w = (const float*)d_in[25];
    const float* mlp1_b = (const float*)d_in[26];
    const float* mlp2_w = (const float*)d_in[27];
    const float* mlp2_b = (const float*)d_in[28];
    float* out = (float*)d_out;

    float *bufA, *bufB, *al1, *al2, *x, *qkv, *att, *tmp, *ff;
    __half *hA, *hW;
    cudaGetSymbolAddress((void**)&bufA, g_bufA);
    cudaGetSymbolAddress((void**)&bufB, g_bufB);
    cudaGetSymbolAddress((void**)&al1,  g_alpha1);
    cudaGetSymbolAddress((void**)&al2,  g_alpha2);
    cudaGetSymbolAddress((void**)&x,    g_x);
    cudaGetSymbolAddress((void**)&qkv,  g_qkv);
    cudaGetSymbolAddress((void**)&att,  g_att);
    cudaGetSymbolAddress((void**)&tmp,  g_tmp);
    cudaGetSymbolAddress((void**)&ff,   g_ff);
    cudaGetSymbolAddress((void**)&hA,   g_hA);
    cudaGetSymbolAddress((void**)&hW,   g_hW);

    static bool attr_done = false;
    if (!attr_done) {
        cudaFuncSetAttribute(attn_kernel,
                             cudaFuncAttributeMaxDynamicSharedMemorySize, ATTN_SMEM);
        cudaFuncSetAttribute(hgemm16_kernel,
                             cudaFuncAttributeMaxDynamicSharedMemorySize, HSMEM);
        attr_done = true;
    }

    // fused convert+GEMM launcher: C = act(A(MxK) @ B(KxN) + bias + res)
    auto gemm = [&](const float* A, const float* B, float* C,
                    int M, int K, int N,
                    const float* bias, const float* res, int relu) {
        int Kp = ((K + HKT - 1)/HKT)*HKT;
        int Npad = ((N + 127)/128)*128;
        size_t ta = (size_t)M*Kp;
        convA_kernel<<<(unsigned)((ta+255)/256),256>>>(A, hA, K, Kp, ta);
        convBt_kernel<<<(Npad*Kp+255)/256,256>>>(B, hW, K, N, Kp, Npad);
        dim3 g(Npad/128, M/128);
        hgemm16_kernel<<<g,128,HSMEM>>>(hA, hW, C, M, N, Kp, bias, res, relu);
    };

    zero_kernel<<<(out_size+255)/256, 256>>>(out, out_size);

    // ----- GAT -----
    {
        size_t nx = (size_t)BATCH*DINP*FIN;
        build_x_kernel<<<(unsigned)((nx+255)/256), 256>>>(src, R_u);
        gemm(bufA, W1, bufB, NROWS_GAT, FIN, FIN, nullptr, nullptr, 0);
        psd_kernel<<<NROWS_GAT,256>>>(bufB, a1_s, a1_d);
        alpha_kernel<<<BATCH,64>>>(nullptr, al1);
        gat_agg_kernel<<<BATCH,256>>>(al1, bufB, bufA);
        gemm(bufA, W2, bufB, NROWS_GAT, FIN, FIN, nullptr, nullptr, 0);
        psd_kernel<<<NROWS_GAT,256>>>(bufB, a2_s, a2_d);
        alpha_kernel<<<BATCH,64>>>(al1, al2);
        gat_agg_kernel<<<BATCH,256>>>(al2, bufB, bufA);
        sq_kernel<<<BATCH,256>>>(al2);
        dist_kernel<<<BATCH,256>>>(al2);
        fin_dist_kernel<<<1,32>>>(out, out_size);
    }

    // ----- transformer -----
    {
        size_t no = (size_t)NROWS_TR*DT;
        build_out_kernel<<<(unsigned)((no+255)/256), 256>>>(times);
        for (int l=0; l<2; l++) {
            gemm(x, attn_in_w + (size_t)l*DT*3*DT, qkv,
                 NROWS_TR, DT, 3*DT, attn_in_b + l*3*DT, nullptr, 0);
            attn_kernel<<<dim3(BATCH,NHEAD),256,ATTN_SMEM>>>(qkv, lengths, att);
            gemm(att, attn_out_w + (size_t)l*DT*DT, tmp,
                 NROWS_TR, DT, DT, attn_out_b + l*DT, x, 0);
            ln_kernel<<<NROWS_TR,DT>>>(tmp, x, ln1_g + l*DT, ln1_b + l*DT);
            gemm(x, ff1_w + (size_t)l*DT*NHID, ff,
                 NROWS_TR, DT, NHID, ff1_b + l*NHID, nullptr, 1);
            gemm(ff, ff2_w + (size_t)l*NHID*DT, tmp,
                 NROWS_TR, NHID, DT, ff2_b + l*DT, x, 0);
            ln_kernel<<<NROWS_TR,DT>>>(tmp, x, ln2_g + l*DT, ln2_b + l*DT);
        }
    }

    // ----- head -----
    agg_emb_kernel<<<BATCH,DFINAL>>>(lengths, statics, emb_w, emb_b);
    mlp_kernel<<<BATCH,DFINAL>>>(mlp1_w, mlp1_b, mlp2_w, mlp2_b, out);
}

// round 9
// speedup vs baseline: 1.1011x; 1.0730x over previous
#include <cuda_runtime.h>
#include <cuda_fp16.h>
#include <cstdint>
#include <math.h>
#include <mma.h>
using namespace nvcuda;

// ---------------- model constants ----------------
#define BATCH   512
#define S_LEN   215
#define DINP    36
#define DMODEL  144
#define DT      160
#define NHEAD   4
#define DH      40
#define NHID    128
#define FIN     860
#define FINP    896          // FIN padded to 64
#define DTP     192          // DT padded to 64
#define DFINAL  196
#define NROWS_GAT (BATCH*DINP)          // 18432
#define NROWS_TR  (S_LEN*BATCH)         // 110080

// ---------------- scratch (device globals) ----------------
__device__ float  g_bufA[(size_t)NROWS_GAT*FIN];       // H2 fp32 (feeds build_out)
__device__ float  g_ps[NROWS_GAT];
__device__ float  g_pd[NROWS_GAT];
__device__ float  g_alpha1[(size_t)BATCH*DINP*DINP];
__device__ float  g_alpha2[(size_t)BATCH*DINP*DINP];
__device__ float  g_sq[BATCH];
__device__ float  g_part[BATCH];
__device__ float  g_x[(size_t)NROWS_TR*DT];            // residual stream fp32
__device__ float  g_tmp[(size_t)NROWS_TR*DT];
__device__ float  g_feat[BATCH*DFINAL];
// fp16 operands / intermediates
__device__ __half g_hgat[(size_t)NROWS_GAT*FINP];      // GAT A operand (X then H1)
__device__ __half g_hXP[(size_t)NROWS_GAT*FIN];        // XP fp16 (ld FIN)
__device__ __half g_hx[(size_t)NROWS_TR*DTP];          // x fp16 mirror (A operand)
__device__ __half g_hatt[(size_t)NROWS_TR*DTP];        // att fp16 (A operand)
__device__ __half g_hff[(size_t)NROWS_TR*NHID];        // ff fp16 (A operand, K=128)
__device__ __half g_qkvh[(size_t)NROWS_TR*3*DT];       // qkv fp16
__device__ __half g_hW[FINP*FINP];                     // transposed weights Npad x Kp

// ---------------- utility ----------------
__global__ void zero_kernel(float* p, int n) {
    int i = blockIdx.x*blockDim.x + threadIdx.x;
    if (i < n) p[i] = 0.f;
}
// zero pad columns [c0,ld) of an fp16 row-major buffer
__global__ void padzero_kernel(__half* p, int rows, int ld, int c0) {
    int w = ld - c0;
    int i = blockIdx.x*blockDim.x + threadIdx.x;
    if (i >= rows*w) return;
    int r = i / w, c = c0 + i % w;
    p[(size_t)r*ld + c] = __float2half(0.f);
}

__device__ __forceinline__ void cp16(uint32_t dst, const void* src) {
    asm volatile("cp.async.cg.shared.global [%0], [%1], 16;\n" :: "r"(dst), "l"(src));
}
__device__ __forceinline__ void cp_commit() {
    asm volatile("cp.async.commit_group;\n" ::: "memory");
}
__device__ __forceinline__ void cp_wait_all() {
    asm volatile("cp.async.wait_group 0;\n" ::: "memory");
}

// ---------------- weight transpose+convert: B(KxN fp32) -> Bt(Npad x Kp fp16) ----------------
__global__ void convBt_kernel(const float* __restrict__ B, __half* __restrict__ dst,
                              int K, int N, int Kp, int Npad)
{
    int i = blockIdx.x*blockDim.x + threadIdx.x;
    if (i >= Npad*Kp) return;
    int k = i % Kp, n = i / Kp;
    dst[i] = __float2half((k < K && n < N) ? B[(size_t)k*N + n] : 0.f);
}

// ---------------- FP16 tensor-core GEMM ----------------
// out = act(Ah@Bt^T + bias + res); writes fp32 Cf and/or fp16 Ch (ld = ldc).
#define HKT 64
#define HLD 72
#define HSTG (128*HLD)
#define HSMEM (4*HSTG*2)
#define WLD 20

__global__ void __launch_bounds__(128)
hgemm16_kernel(const __half* __restrict__ Ah, const __half* __restrict__ Bt,
               float* __restrict__ Cf, __half* __restrict__ Ch,
               int M, int N, int Kp, int ldc,
               const float* __restrict__ bias,
               const float* __restrict__ res, int relu_flag)
{
    extern __shared__ __half hs[];
    __half* As0 = hs;
    __half* Bs0 = hs + HSTG;
    __half* As1 = hs + 2*HSTG;
    __half* Bs1 = hs + 3*HSTG;
    __shared__ float Wb[4][16*WLD];

    int tid = threadIdx.x;
    int warpId = tid >> 5, lane = tid & 31;
    int wr = warpId >> 1, wc = warpId & 1;
    int row0 = blockIdx.y*128, col0 = blockIdx.x*128;

    wmma::fragment<wmma::accumulator,16,16,16,float> cf[4][4];
    #pragma unroll
    for (int i=0;i<4;i++)
      #pragma unroll
      for (int j=0;j<4;j++) wmma::fill_fragment(cf[i][j], 0.f);

    const int nIter = Kp / HKT;

    auto load_stage = [&](__half* as, __half* bs, int k0) {
        #pragma unroll
        for (int c = 0; c < 8; c++) {
            int ci = tid + c*128;
            int r = ci >> 3, c8 = (ci & 7)*8;
            cp16((uint32_t)__cvta_generic_to_shared(&as[r*HLD + c8]),
                 &Ah[(size_t)(row0 + r)*Kp + k0 + c8]);
        }
        #pragma unroll
        for (int c = 0; c < 8; c++) {
            int ci = tid + c*128;
            int r = ci >> 3, c8 = (ci & 7)*8;
            cp16((uint32_t)__cvta_generic_to_shared(&bs[r*HLD + c8]),
                 &Bt[(size_t)(col0 + r)*Kp + k0 + c8]);
        }
        cp_commit();
    };

    load_stage(As0, Bs0, 0);

    for (int it = 0; it < nIter; it++) {
        cp_wait_all();
        __syncthreads();
        __half* as = (it & 1) ? As1 : As0;
        __half* bs = (it & 1) ? Bs1 : Bs0;
        if (it + 1 < nIter)
            load_stage((it & 1) ? As0 : As1, (it & 1) ? Bs0 : Bs1, (it+1)*HKT);

        #pragma unroll
        for (int ks = 0; ks < HKT; ks += 16) {
            wmma::fragment<wmma::matrix_a,16,16,16,__half,wmma::row_major> af[4];
            wmma::fragment<wmma::matrix_b,16,16,16,__half,wmma::col_major> bf[4];
            #pragma unroll
            for (int fr=0; fr<4; fr++)
                wmma::load_matrix_sync(af[fr], &as[(wr*64 + fr*16)*HLD + ks], HLD);
            #pragma unroll
            for (int fc=0; fc<4; fc++)
                wmma::load_matrix_sync(bf[fc], &bs[(wc*64 + fc*16)*HLD + ks], HLD);
            #pragma unroll
            for (int fr=0; fr<4; fr++)
              #pragma unroll
              for (int fc=0; fc<4; fc++)
                wmma::mma_sync(cf[fr][fc], af[fr], bf[fc], cf[fr][fc]);
        }
        __syncthreads();
    }

    float* wbuf = Wb[warpId];
    #pragma unroll
    for (int fr=0; fr<4; fr++) {
        #pragma unroll
        for (int fc=0; fc<4; fc++) {
            wmma::store_matrix_sync(wbuf, cf[fr][fc], WLD, wmma::mem_row_major);
            __syncwarp();
            int rb = row0 + wr*64 + fr*16;
            int cb = col0 + wc*64 + fc*16;
            #pragma unroll
            for (int i = lane; i < 256; i += 32) {
                int r = i >> 4, c = i & 15;
                int gc = cb + c;
                if (gc < N) {
                    float v = wbuf[r*WLD + c];
                    if (bias) v += bias[gc];
                    if (res)  v += res[(size_t)(rb + r)*N + gc];
                    if (relu_flag) v = fmaxf(v, 0.f);
                    size_t off = (size_t)(rb + r)*ldc + gc;
                    if (Cf) Cf[off] = v;
                    if (Ch) Ch[off] = __float2half(v);
                }
            }
            __syncwarp();
        }
    }
}

// ---------------- GAT ----------------
// write X directly as fp16 GEMM operand (ld FINP, pads pre-zeroed)
__global__ void build_x_kernel(const float* __restrict__ src, const float* __restrict__ R_u)
{
    size_t n = (size_t)blockIdx.x*blockDim.x + threadIdx.x;
    const size_t total = (size_t)NROWS_GAT*FIN;
    if (n >= total) return;
    int c = (int)(n % FIN);
    int row = (int)(n / FIN);
    int i = row % DINP, b = row / DINP;
    int s = c >> 2, o = c & 3;
    float v = src[((size_t)s*BATCH + b)*(2*DINP) + i];
    g_hgat[(size_t)row*FINP + c] = __float2half(fmaxf(v * R_u[i*4+o], 0.f));
}

__global__ void psd_kernel(const __half* __restrict__ XP,
                           const float* __restrict__ a_s, const float* __restrict__ a_d)
{
    int row = blockIdx.x;
    const __half* x = XP + (size_t)row*FIN;
    int t = threadIdx.x;
    float s1=0.f, s2=0.f;
    for (int c=t; c<FIN; c+=256) { float v=__half2float(x[c]); s1 += v*a_s[c]; s2 += v*a_d[c]; }
    __shared__ float r1[256], r2[256];
    r1[t]=s1; r2[t]=s2; __syncthreads();
    for (int o=128;o>0;o>>=1){ if(t<o){r1[t]+=r1[t+o]; r2[t]+=r2[t+o];} __syncthreads(); }
    if (t==0){ g_ps[row]=r1[0]; g_pd[row]=r2[0]; }
}

__global__ void alpha_kernel(const float* __restrict__ edge, float* __restrict__ alpha)
{
    int b = blockIdx.x;
    int i = threadIdx.x;
    if (i >= DINP) return;
    const float* psb = g_ps + b*DINP;
    float pdi = g_pd[b*DINP+i];
    float e[DINP];
    float m = -1e30f;
    #pragma unroll
    for (int j=0;j<DINP;j++){
        float v = pdi + psb[j];
        v = (v > 0.f) ? v : 0.2f*v;
        e[j]=v; m = fmaxf(m,v);
    }
    float l=0.f;
    #pragma unroll
    for (int j=0;j<DINP;j++){ float w=expf(e[j]-m); e[j]=w; l+=w; }
    float inv = 1.f/l;
    size_t base = ((size_t)b*DINP + i)*DINP;
    #pragma unroll
    for (int j=0;j<DINP;j++){
        float a = e[j]*inv;
        if (edge) a *= edge[base+j];
        alpha[base+j] = a;
    }
}

// H = alpha @ XP ; write fp16 (ld FINP) and/or fp32 (ld FIN)
__global__ void gat_agg_kernel(const float* __restrict__ alpha, const __half* __restrict__ XP,
                               __half* __restrict__ Hh, float* __restrict__ Hf)
{
    int b = blockIdx.x;
    __shared__ float al[DINP*DINP];
    for (int i=threadIdx.x;i<DINP*DINP;i+=blockDim.x) al[i]=alpha[(size_t)b*DINP*DINP+i];
    __syncthreads();
    const __half* xp = XP + (size_t)b*DINP*FIN;
    for (int idx=threadIdx.x; idx<DINP*FIN; idx+=blockDim.x){
        int i = idx/FIN, c = idx%FIN;
        float s=0.f;
        #pragma unroll 6
        for (int j=0;j<DINP;j++) s += al[i*DINP+j]*__half2float(xp[(size_t)j*FIN+c]);
        size_t row = (size_t)b*DINP + i;
        if (Hh) Hh[row*FINP + c] = __float2half(s);
        if (Hf) Hf[row*FIN + c] = s;
    }
}

__global__ void sq_kernel(const float* __restrict__ A)
{
    int b = blockIdx.x; int t = threadIdx.x;
    float s=0.f;
    for (int i=t;i<DINP*DINP;i+=256){ float v=A[(size_t)b*DINP*DINP+i]; s+=v*v; }
    __shared__ float r[256];
    r[t]=s; __syncthreads();
    for (int o=128;o>0;o>>=1){ if(t<o) r[t]+=r[t+o]; __syncthreads(); }
    if (t==0) g_sq[b]=r[0];
}

__global__ void dist_kernel(const float* __restrict__ A)
{
    int i = blockIdx.x; int t = threadIdx.x;
    __shared__ float Ai[DINP*DINP];
    for (int c=t;c<DINP*DINP;c+=256) Ai[c]=A[(size_t)i*DINP*DINP+c];
    __syncthreads();
    float local=0.f;
    for (int j=t;j<BATCH;j+=256){
        const float* Aj = A + (size_t)j*DINP*DINP;
        float dot=0.f;
        for (int c=0;c<DINP*DINP;c++) dot += Ai[c]*Aj[c];
        float d2 = g_sq[i]+g_sq[j]-2.f*dot;
        d2 = fmaxf(d2, 0.f);
        local += sqrtf(d2 + 1e-12f);
    }
    __shared__ float r[256];
    r[t]=local; __syncthreads();
    for (int o=128;o>0;o>>=1){ if(t<o) r[t]+=r[t+o]; __syncthreads(); }
    if (t==0) g_part[i]=r[0];
}

__global__ void fin_dist_kernel(float* __restrict__ out, int out_size)
{
    if (threadIdx.x==0){
        float s=0.f;
        for (int i=0;i<BATCH;i++) s += g_part[i];
        if (out_size > BATCH*2) out[BATCH*2] = s / ((float)BATCH*(float)BATCH);
    }
}

// ---------------- transformer input: fp32 x + fp16 mirror ----------------
__global__ void build_out_kernel(const float* __restrict__ times)
{
    size_t n = (size_t)blockIdx.x*blockDim.x + threadIdx.x;
    const size_t total = (size_t)NROWS_TR*DT;
    if (n >= total) return;
    int d = (int)(n % DT);
    size_t row = n / DT;
    int b = (int)(row % BATCH);
    int s = (int)(row / BATCH);
    float v;
    if (d < DMODEL) {
        v = g_bufA[((size_t)b*DINP + (d>>2))*FIN + s*4 + (d&3)];
    } else {
        int k = d - DMODEL;
        float tv = times[(size_t)s*BATCH + b];
        int kk = (k < 8) ? k : k-8;
        float ts = powf(215.0f, (float)kk/7.0f) * 100.0f;
        float sc = tv / ts;
        v = (k < 8) ? sinf(sc) : cosf(sc);
    }
    g_x[n] = v;
    g_hx[row*DTP + d] = __float2half(v);
}

// ---------------- attention (fp16 qkv in, fp16 out) ----------------
#define ATTN_SMEM (2*S_LEN*DH*4)
__global__ void attn_kernel(const __half* __restrict__ qkv, const int* __restrict__ lengths,
                            __half* __restrict__ outh)
{
    extern __shared__ float smA[];
    float* Ks = smA;
    float* Vs = smA + S_LEN*DH;
    int b = blockIdx.x, h = blockIdx.y;
    int len = lengths[b];
    for (int i = threadIdx.x; i < S_LEN*DH; i += blockDim.x) {
        int t = i / DH, d = i % DH;
        size_t base = ((size_t)t*BATCH + b)*(3*DT) + h*DH + d;
        Ks[i] = __half2float(qkv[base + DT]);
        Vs[i] = __half2float(qkv[base + 2*DT]);
    }
    __syncthreads();
    int s = threadIdx.x;
    if (s >= S_LEN) return;
    float q[DH];
    {
        size_t qb = ((size_t)s*BATCH + b)*(3*DT) + h*DH;
        #pragma unroll
        for (int d=0; d<DH; d++) q[d] = __half2float(qkv[qb + d]);
    }
    const float scale = rsqrtf((float)DH);
    float l = 0.f;
    float acc[DH];
    #pragma unroll
    for (int d=0; d<DH; d++) acc[d]=0.f;
    for (int t=0; t<len; t++) {
        float sc = 0.f;
        #pragma unroll
        for (int d=0; d<DH; d++) sc += q[d]*Ks[t*DH+d];
        float w = expf(sc*scale);
        l += w;
        #pragma unroll
        for (int d=0; d<DH; d++) acc[d] += w*Vs[t*DH+d];
    }
    float inv = 1.f/l;
    size_t ob = ((size_t)s*BATCH + b)*DTP + h*DH;
    #pragma unroll
    for (int d=0; d<DH; d++) outh[ob + d] = __float2half(acc[d]*inv);
}

// ---------------- layernorm: fp32 out + fp16 mirror ----------------
__global__ void ln_kernel(const float* __restrict__ x, float* __restrict__ y,
                          __half* __restrict__ yh,
                          const float* __restrict__ g, const float* __restrict__ bta)
{
    int row = blockIdx.x;
    const float* xr = x + (size_t)row*DT;
    int t = threadIdx.x;
    float v = xr[t];
    __shared__ float s1[DT], s2[DT];
    s1[t]=v; s2[t]=v*v; __syncthreads();
    if (t < 32) {
        float a=0.f, q=0.f;
        for (int i=t;i<DT;i+=32){ a+=s1[i]; q+=s2[i]; }
        for (int o=16;o>0;o>>=1){ a+=__shfl_down_sync(0xffffffff,a,o); q+=__shfl_down_sync(0xffffffff,q,o); }
        if (t==0){ s1[0]=a; s2[0]=q; }
    }
    __syncthreads();
    float mean = s1[0]/(float)DT;
    float var  = s2[0]/(float)DT - mean*mean;
    float r = (v-mean)*rsqrtf(var+1e-5f)*g[t] + bta[t];
    y[(size_t)row*DT + t] = r;
    yh[(size_t)row*DTP + t] = __float2half(r);
}

// ---------------- pooled features + static embedding ----------------
__global__ void agg_emb_kernel(const int* __restrict__ lengths,
                               const float* __restrict__ statics,
                               const float* __restrict__ emb_w, const float* __restrict__ emb_b)
{
    int b = blockIdx.x; int d = threadIdx.x;
    int len = lengths[b];
    if (d < DT) {
        float s = 0.f;
        for (int t=0;t<len;t++) s += g_x[((size_t)t*BATCH + b)*DT + d];
        g_feat[b*DFINAL+d] = s / ((float)len + 1.0f);
    } else if (d < DFINAL) {
        int j = d - DT;
        float s = emb_b[j];
        #pragma unroll
        for (int r=0;r<9;r++) s += statics[b*9+r]*emb_w[r*DINP+j];
        g_feat[b*DFINAL+d] = s;
    }
}

// ---------------- final MLP ----------------
__global__ void mlp_kernel(const float* __restrict__ w1, const float* __restrict__ b1,
                           const float* __restrict__ w2, const float* __restrict__ b2,
                           float* __restrict__ out)
{
    int b = blockIdx.x; int t = threadIdx.x;
    __shared__ float f[DFINAL], hd[DFINAL];
    f[t] = g_feat[b*DFINAL+t];
    __syncthreads();
    float s = b1[t];
    for (int r=0;r<DFINAL;r++) s += f[r]*w1[r*DFINAL+t];
    hd[t] = fmaxf(s, 0.f);
    __syncthreads();
    if (t < 2) {
        float s2 = b2[t];
        for (int r=0;r<DFINAL;r++) s2 += hd[r]*w2[r*2+t];
        out[b*2+t] = s2;
    }
}

// ---------------- launch ----------------
extern "C" void kernel_launch(void* const* d_in, const int* in_sizes, int n_in,
                              void* d_out, int out_size)
{
    const float* src    = (const float*)d_in[0];
    const float* statics= (const float*)d_in[1];
    const float* times  = (const float*)d_in[2];
    const int*   lengths= (const int*)d_in[3];
    const float* R_u    = (const float*)d_in[4];
    const float* emb_w  = (const float*)d_in[5];
    const float* emb_b  = (const float*)d_in[6];
    const float* W1     = (const float*)d_in[7];
    const float* a1_s   = (const float*)d_in[8];
    const float* a1_d   = (const float*)d_in[9];
    const float* W2     = (const float*)d_in[10];
    const float* a2_s   = (const float*)d_in[11];
    const float* a2_d   = (const float*)d_in[12];
    const float* attn_in_w  = (const float*)d_in[13];
    const float* attn_in_b  = (const float*)d_in[14];
    const float* attn_out_w = (const float*)d_in[15];
    const float* attn_out_b = (const float*)d_in[16];
    const float* ff1_w  = (const float*)d_in[17];
    const float* ff1_b  = (const float*)d_in[18];
    const float* ff2_w  = (const float*)d_in[19];
    const float* ff2_b  = (const float*)d_in[20];
    const float* ln1_g  = (const float*)d_in[21];
    const float* ln1_b  = (const float*)d_in[22];
    const float* ln2_g  = (const float*)d_in[23];
    const float* ln2_b  = (const float*)d_in[24];
    const float* mlp1_w = (const float*)d_in[25];
    const float* mlp1_b = (const float*)d_in[26];
    const float* mlp2_w = (const float*)d_in[27];
    const float* mlp2_b = (const float*)d_in[28];
    float* out = (float*)d_out;

    float *bufA, *al1, *al2, *x, *tmp;
    __half *hgat, *hXP, *hx, *hatt, *hff, *qkvh, *hW;
    cudaGetSymbolAddress((void**)&bufA, g_bufA);
    cudaGetSymbolAddress((void**)&al1,  g_alpha1);
    cudaGetSymbolAddress((void**)&al2,  g_alpha2);
    cudaGetSymbolAddress((void**)&x,    g_x);
    cudaGetSymbolAddress((void**)&tmp,  g_tmp);
    cudaGetSymbolAddress((void**)&hgat, g_hgat);
    cudaGetSymbolAddress((void**)&hXP,  g_hXP);
    cudaGetSymbolAddress((void**)&hx,   g_hx);
    cudaGetSymbolAddress((void**)&hatt, g_hatt);
    cudaGetSymbolAddress((void**)&hff,  g_hff);
    cudaGetSymbolAddress((void**)&qkvh, g_qkvh);
    cudaGetSymbolAddress((void**)&hW,   g_hW);

    static bool attr_done = false;
    if (!attr_done) {
        cudaFuncSetAttribute(attn_kernel,
                             cudaFuncAttributeMaxDynamicSharedMemorySize, ATTN_SMEM);
        cudaFuncSetAttribute(hgemm16_kernel,
                             cudaFuncAttributeMaxDynamicSharedMemorySize, HSMEM);
        attr_done = true;
    }

    // GEMM: out = act(A(M x K, fp16 padded ld Kp) @ B(KxN fp32) + bias + res)
    auto gemm = [&](const __half* Ah, const float* B, float* Cf, __half* Ch,
                    int M, int K, int N, int ldc,
                    const float* bias, const float* res, int relu) {
        int Kp = ((K + HKT - 1)/HKT)*HKT;
        int Npad = ((N + 127)/128)*128;
        convBt_kernel<<<(Npad*Kp+255)/256,256>>>(B, hW, K, N, Kp, Npad);
        dim3 g(Npad/128, M/128);
        hgemm16_kernel<<<g,128,HSMEM>>>(Ah, hW, Cf, Ch, M, N, Kp, ldc, bias, res, relu);
    };

    zero_kernel<<<(out_size+255)/256, 256>>>(out, out_size);
    // zero pad columns of fp16 A operands (deterministic every call)
    padzero_kernel<<<(NROWS_GAT*(FINP-FIN)+255)/256,256>>>(hgat, NROWS_GAT, FINP, FIN);
    padzero_kernel<<<(NROWS_TR*(DTP-DT)+255)/256,256>>>(hx, NROWS_TR, DTP, DT);
    padzero_kernel<<<(NROWS_TR*(DTP-DT)+255)/256,256>>>(hatt, NROWS_TR, DTP, DT);

    // ----- GAT -----
    {
        size_t nx = (size_t)NROWS_GAT*FIN;
        build_x_kernel<<<(unsigned)((nx+255)/256), 256>>>(src, R_u);
        gemm(hgat, W1, nullptr, hXP, NROWS_GAT, FIN, FIN, FIN, nullptr, nullptr, 0);
        psd_kernel<<<NROWS_GAT,256>>>(hXP, a1_s, a1_d);
        alpha_kernel<<<BATCH,64>>>(nullptr, al1);
        gat_agg_kernel<<<BATCH,256>>>(al1, hXP, hgat, nullptr);
        gemm(hgat, W2, nullptr, hXP, NROWS_GAT, FIN, FIN, FIN, nullptr, nullptr, 0);
        psd_kernel<<<NROWS_GAT,256>>>(hXP, a2_s, a2_d);
        alpha_kernel<<<BATCH,64>>>(al1, al2);
        gat_agg_kernel<<<BATCH,256>>>(al2, hXP, nullptr, bufA);
        sq_kernel<<<BATCH,256>>>(al2);
        dist_kernel<<<BATCH,256>>>(al2);
        fin_dist_kernel<<<1,32>>>(out, out_size);
    }

    // ----- transformer -----
    {
        size_t no = (size_t)NROWS_TR*DT;
        build_out_kernel<<<(unsigned)((no+255)/256), 256>>>(times);
        for (int l=0; l<2; l++) {
            gemm(hx, attn_in_w + (size_t)l*DT*3*DT, nullptr, qkvh,
                 NROWS_TR, DT, 3*DT, 3*DT, attn_in_b + l*3*DT, nullptr, 0);
            attn_kernel<<<dim3(BATCH,NHEAD),256,ATTN_SMEM>>>(qkvh, lengths, hatt);
            gemm(hatt, attn_out_w + (size_t)l*DT*DT, tmp, nullptr,
                 NROWS_TR, DT, DT, DT, attn_out_b + l*DT, x, 0);
            ln_kernel<<<NROWS_TR,DT>>>(tmp, x, hx, ln1_g + l*DT, ln1_b + l*DT);
            gemm(hx, ff1_w + (size_t)l*DT*NHID, nullptr, hff,
                 NROWS_TR, DT, NHID, NHID, ff1_b + l*NHID, nullptr, 1);
            gemm(hff, ff2_w + (size_t)l*NHID*DT, tmp, nullptr,
                 NROWS_TR, NHID, DT, DT, ff2_b + l*DT, x, 0);
            ln_kernel<<<NROWS_TR,DT>>>(tmp, x, hx, ln2_g + l*DT, ln2_b + l*DT);
        }
    }

    // ----- head -----
    agg_emb_kernel<<<BATCH,DFINAL>>>(lengths, statics, emb_w, emb_b);
    mlp_kernel<<<BATCH,DFINAL>>>(mlp1_w, mlp1_b, mlp2_w, mlp2_b, out);
}